// round 1
// baseline (speedup 1.0000x reference)
#include <cuda_runtime.h>
#include <math.h>

// Problem constants (fixed shapes from reference)
#define S_LEN   2048
#define DH      64
#define NB      2
#define NH      8
#define WIN     128     // |i-j| < 128
#define TQ      64      // queries per block
#define NCHUNK  9       // ceil((255+7)/32) key chunks per warp

// Shared memory layout (floats)
#define KTS     353                 // K^T row stride (64 rows of up to 352 keys, odd stride -> conflict-free)
#define KTROWS  352
#define QTS     68                  // Q^T row stride (mult of 4 for float4 reads, +4 pad)
#define SM_KT   (DH * KTS)          // 22592
#define SM_VS   (KTROWS * DH)       // 22528
#define SM_QT   (DH * QTS)          // 4352
#define SM_PS   (8 * 256)           // per-warp p staging: 32 keys x 8 queries
#define SM_FLOATS (SM_KT + SM_VS + SM_QT + SM_PS)
#define SMEM_BYTES (SM_FLOATS * 4)  // 206080 bytes

__global__ void __launch_bounds__(256, 1)
band_attn_kernel(const float* __restrict__ Q,
                 const float* __restrict__ K,
                 const float* __restrict__ V,
                 float* __restrict__ ctx_out,
                 float* __restrict__ attn_out)
{
    extern __shared__ float smem[];
    float* Kt = smem;                 // [DH][KTS]  (K transposed: Kt[d*KTS + kk])
    float* Vs = Kt + SM_KT;           // [KTROWS][DH] natural
    float* Qt = Vs + SM_VS;           // [DH][QTS]  (Q transposed: Qt[d*QTS + q])
    float* Ps = Qt + SM_QT;           // per-warp staging [8 warps][32 keys][8 q]

    const int tid  = threadIdx.x;
    const int w    = tid >> 5;
    const int lane = tid & 31;
    const int bh   = blockIdx.z * NH + blockIdx.y;
    const int q0   = blockIdx.x * TQ;

    const int k_lo = max(0, q0 - (WIN - 1));
    const int k_hi = min(S_LEN - 1, q0 + TQ - 1 + (WIN - 1));
    const int cnt  = k_hi - k_lo + 1;   // <= 318

    const float* Qg = Q + (size_t)bh * S_LEN * DH;
    const float* Kg = K + (size_t)bh * S_LEN * DH;
    const float* Vg = V + (size_t)bh * S_LEN * DH;

    // ---- load tiles into smem ----
    for (int idx = tid; idx < TQ * DH; idx += 256) {
        int q = idx >> 6, d = idx & 63;
        Qt[d * QTS + q] = Qg[(size_t)(q0 + q) * DH + d];
    }
    for (int idx = tid; idx < cnt * DH; idx += 256) {
        int kk = idx >> 6, d = idx & 63;
        Kt[d * KTS + kk] = Kg[(size_t)(k_lo + kk) * DH + d];
    }
    {
        const float4* src = (const float4*)(Vg + (size_t)k_lo * DH);
        float4* dst = (float4*)Vs;
        for (int idx = tid; idx < cnt * (DH / 4); idx += 256) dst[idx] = src[idx];
    }
    __syncthreads();

    // ---- per-warp: 8 consecutive queries ----
    const int qbase = w * 8;            // local query base
    const int qg0   = q0 + qbase;       // global query base
    const int a = max(0, qg0 - (WIN - 1)) - k_lo;                  // union window lo (tile coords)
    const int b = min(S_LEN - 1, qg0 + 7 + (WIN - 1)) - k_lo;      // union window hi

    // ---- scores: d-outer, K read once per (d, chunk), shared by 8 queries ----
    float sc[NCHUNK][8];
    #pragma unroll
    for (int c = 0; c < NCHUNK; ++c)
        #pragma unroll
        for (int i = 0; i < 8; ++i) sc[c][i] = 0.f;

    #pragma unroll 4
    for (int d = 0; d < DH; ++d) {
        const float4 qA = *(const float4*)(Qt + d * QTS + qbase);
        const float4 qB = *(const float4*)(Qt + d * QTS + qbase + 4);
        const float* Krow = Kt + d * KTS + a + lane;
        #pragma unroll
        for (int c = 0; c < NCHUNK; ++c) {
            float kv = Krow[c * 32];   // may be garbage past b: masked below
            sc[c][0] += qA.x * kv; sc[c][1] += qA.y * kv;
            sc[c][2] += qA.z * kv; sc[c][3] += qA.w * kv;
            sc[c][4] += qB.x * kv; sc[c][5] += qB.y * kv;
            sc[c][6] += qB.z * kv; sc[c][7] += qB.w * kv;
        }
    }

    // ---- scale + band mask ----
    #pragma unroll
    for (int c = 0; c < NCHUNK; ++c) {
        int kk = a + c * 32 + lane;
        int k  = k_lo + kk;
        #pragma unroll
        for (int i = 0; i < 8; ++i) {
            int qg = qg0 + i;
            bool vld = (kk <= b) && (k >= qg - (WIN - 1)) && (k <= qg + (WIN - 1));
            sc[c][i] = vld ? sc[c][i] * 0.125f : -INFINITY;
        }
    }

    // ---- softmax per query (warp-wide) ----
    #pragma unroll
    for (int i = 0; i < 8; ++i) {
        float m = -INFINITY;
        #pragma unroll
        for (int c = 0; c < NCHUNK; ++c) m = fmaxf(m, sc[c][i]);
        #pragma unroll
        for (int off = 16; off > 0; off >>= 1)
            m = fmaxf(m, __shfl_xor_sync(0xffffffffu, m, off));
        float s = 0.f;
        #pragma unroll
        for (int c = 0; c < NCHUNK; ++c) {
            float e = __expf(sc[c][i] - m);
            sc[c][i] = e; s += e;
        }
        #pragma unroll
        for (int off = 16; off > 0; off >>= 1)
            s += __shfl_xor_sync(0xffffffffu, s, off);
        float inv = 1.f / s;
        #pragma unroll
        for (int c = 0; c < NCHUNK; ++c) sc[c][i] *= inv;
    }

    // ---- write attn band (zeros elsewhere come from the memset node) ----
    float* attn_base = attn_out + (size_t)bh * S_LEN * S_LEN;
    #pragma unroll
    for (int c = 0; c < NCHUNK; ++c) {
        int kk = a + c * 32 + lane;
        int k  = k_lo + kk;
        #pragma unroll
        for (int i = 0; i < 8; ++i) {
            int qg = qg0 + i;
            if ((kk <= b) && (k >= qg - (WIN - 1)) && (k <= qg + (WIN - 1)))
                attn_base[(size_t)qg * S_LEN + k] = sc[c][i];
        }
    }

    // ---- context: p broadcast via per-warp smem staging, V read once per key for 8 queries ----
    float c0[8], c1[8];
    #pragma unroll
    for (int i = 0; i < 8; ++i) { c0[i] = 0.f; c1[i] = 0.f; }

    float* myPs = Ps + w * 256;
    #pragma unroll
    for (int c = 0; c < NCHUNK; ++c) {
        *(float4*)(myPs + lane * 8)     = make_float4(sc[c][0], sc[c][1], sc[c][2], sc[c][3]);
        *(float4*)(myPs + lane * 8 + 4) = make_float4(sc[c][4], sc[c][5], sc[c][6], sc[c][7]);
        __syncwarp();
        const int kkb = a + c * 32;
        const int nk  = min(32, b - kkb + 1);   // uniform across warp
        for (int j = 0; j < nk; ++j) {
            float4 pA = *(const float4*)(myPs + j * 8);
            float4 pB = *(const float4*)(myPs + j * 8 + 4);
            float v0 = Vs[(kkb + j) * DH + lane];
            float v1 = Vs[(kkb + j) * DH + lane + 32];
            c0[0] += pA.x * v0; c1[0] += pA.x * v1;
            c0[1] += pA.y * v0; c1[1] += pA.y * v1;
            c0[2] += pA.z * v0; c1[2] += pA.z * v1;
            c0[3] += pA.w * v0; c1[3] += pA.w * v1;
            c0[4] += pB.x * v0; c1[4] += pB.x * v1;
            c0[5] += pB.y * v0; c1[5] += pB.y * v1;
            c0[6] += pB.z * v0; c1[6] += pB.z * v1;
            c0[7] += pB.w * v0; c1[7] += pB.w * v1;
        }
        __syncwarp();
    }

    float* ctx_base = ctx_out + ((size_t)bh * S_LEN + qg0) * DH;
    #pragma unroll
    for (int i = 0; i < 8; ++i) {
        ctx_base[i * DH + lane]      = c0[i];
        ctx_base[i * DH + lane + 32] = c1[i];
    }
}

extern "C" void kernel_launch(void* const* d_in, const int* in_sizes, int n_in,
                              void* d_out, int out_size)
{
    const float* Q = (const float*)d_in[0];
    const float* K = (const float*)d_in[1];
    const float* V = (const float*)d_in[2];

    float* out  = (float*)d_out;
    float* ctx  = out;                                        // [B,H,S,D] first
    float* attn = out + (size_t)NB * NH * S_LEN * DH;         // then [B,H,S,S]

    // Zero everything (attn outside the band must be exactly 0; d_out is poisoned).
    cudaMemsetAsync(d_out, 0, (size_t)out_size * sizeof(float), 0);

    cudaFuncSetAttribute(band_attn_kernel,
                         cudaFuncAttributeMaxDynamicSharedMemorySize, SMEM_BYTES);

    dim3 grid(S_LEN / TQ, NH, NB);
    band_attn_kernel<<<grid, 256, SMEM_BYTES>>>(Q, K, V, ctx, attn);
}

// round 2
// speedup vs baseline: 1.1763x; 1.1763x over previous
#include <cuda_runtime.h>
#include <math.h>

#define S_LEN   2048
#define DH      64
#define NB      2
#define NH      8
#define WIN     128
#define TQ      64
#define NTHREADS 512
#define NCHUNK  9

// Shared memory layout (floats)
#define KTS     353                  // K^T row stride (odd -> conflict-free)
#define KTROWS  352
#define QTS     68
#define SM_KT   (DH * KTS)           // 22592
#define SM_VS   (KTROWS * DH)        // 22528 (stored as float2 interleaved)
#define SM_QT   (DH * QTS)           // 4352
#define SM_PS   (16 * 128)           // per-warp p staging: 32 keys x 4 q
#define SM_FLOATS (SM_KT + SM_VS + SM_QT + SM_PS)
#define SMEM_BYTES (SM_FLOATS * 4)   // 206080

// packed f32x2 FMA: d = a*b + d  (sm_100+ FFMA2)
__device__ __forceinline__ void ffma2(float2& d, float2 a, float2 b) {
    asm("{\n\t"
        ".reg .b64 ra, rb, rd;\n\t"
        "mov.b64 ra, {%2, %3};\n\t"
        "mov.b64 rb, {%4, %5};\n\t"
        "mov.b64 rd, {%0, %1};\n\t"
        "fma.rn.f32x2 rd, ra, rb, rd;\n\t"
        "mov.b64 {%0, %1}, rd;\n\t"
        "}"
        : "+f"(d.x), "+f"(d.y)
        : "f"(a.x), "f"(a.y), "f"(b.x), "f"(b.y));
}

__global__ void __launch_bounds__(NTHREADS, 1)
band_attn_kernel(const float* __restrict__ Q,
                 const float* __restrict__ K,
                 const float* __restrict__ V,
                 float* __restrict__ ctx_out,
                 float* __restrict__ attn_out)
{
    extern __shared__ float smem[];
    float*  Kt  = smem;               // [DH][KTS]
    float2* Vs2 = (float2*)(Kt + SM_KT);  // [KTROWS][32]: (v[d], v[d+32])
    float*  Qt  = (float*)(Vs2) + SM_VS;  // [DH][QTS]
    float*  Ps  = Qt + SM_QT;             // [16 warps][128]

    const int tid  = threadIdx.x;
    const int w    = tid >> 5;
    const int lane = tid & 31;
    const int bh   = blockIdx.z * NH + blockIdx.y;
    const int q0   = blockIdx.x * TQ;

    const int k_lo = max(0, q0 - (WIN - 1));
    const int k_hi = min(S_LEN - 1, q0 + TQ - 1 + (WIN - 1));
    const int cnt  = k_hi - k_lo + 1;   // <= 318

    // ---- zero-fill attn rows outside band (replaces memset; overlaps compute) ----
    float* attn_base = attn_out + (size_t)bh * S_LEN * S_LEN;
    {
        float* tile0 = attn_base + (size_t)q0 * S_LEN;
        const int m = tid;              // float4 chunk index within a row (0..511)
        const float4 z4 = make_float4(0.f, 0.f, 0.f, 0.f);
        #pragma unroll 4
        for (int r = 0; r < TQ; ++r) {
            int qg = q0 + r;
            int lo = max(0, qg - (WIN - 1));
            int hi = min(S_LEN - 1, qg + (WIN - 1));
            if (4 * m + 3 < lo || 4 * m > hi)
                ((float4*)(tile0 + (size_t)r * S_LEN))[m] = z4;
        }
        if (tid < TQ) {                 // boundary chunks: scalar zeros outside band
            int qg = q0 + tid;
            int lo = max(0, qg - (WIN - 1));
            int hi = min(S_LEN - 1, qg + (WIN - 1));
            float* row = tile0 + (size_t)tid * S_LEN;
            for (int c = lo & ~3; c < lo; ++c) row[c] = 0.f;
            int e = (hi + 4) & ~3;
            if (e > S_LEN) e = S_LEN;
            for (int c = hi + 1; c < e; ++c) row[c] = 0.f;
        }
    }

    const float* Qg = Q + (size_t)bh * S_LEN * DH;
    const float* Kg = K + (size_t)bh * S_LEN * DH;
    const float* Vg = V + (size_t)bh * S_LEN * DH;

    // ---- load tiles ----
    for (int idx = tid; idx < TQ * DH; idx += NTHREADS) {
        int q = idx >> 6, d = idx & 63;
        Qt[d * QTS + q] = Qg[(size_t)(q0 + q) * DH + d];
    }
    for (int idx = tid; idx < cnt * DH; idx += NTHREADS) {
        int kk = idx >> 6, d = idx & 63;
        Kt[d * KTS + kk] = Kg[(size_t)(k_lo + kk) * DH + d];
    }
    for (int idx = tid; idx < cnt * 32; idx += NTHREADS) {
        int kk = idx >> 5, l = idx & 31;
        Vs2[kk * 32 + l] = make_float2(Vg[(size_t)(k_lo + kk) * DH + l],
                                       Vg[(size_t)(k_lo + kk) * DH + l + 32]);
    }
    __syncthreads();

    // ---- per-warp: 4 consecutive queries ----
    const int qbase = w * 4;
    const int qg0   = q0 + qbase;
    const int a = max(0, qg0 - (WIN - 1)) - k_lo;
    const int b = min(S_LEN - 1, qg0 + 3 + (WIN - 1)) - k_lo;

    // ---- scores (packed f32x2: two queries per FMA) ----
    float2 s01[NCHUNK], s23[NCHUNK];
    #pragma unroll
    for (int c = 0; c < NCHUNK; ++c) {
        s01[c] = make_float2(0.f, 0.f);
        s23[c] = make_float2(0.f, 0.f);
    }

    #pragma unroll 4
    for (int d = 0; d < DH; ++d) {
        const float4 qv = *(const float4*)(Qt + d * QTS + qbase);
        const float2 q01 = make_float2(qv.x, qv.y);
        const float2 q23 = make_float2(qv.z, qv.w);
        const float* Krow = Kt + d * KTS + a + lane;
        #pragma unroll
        for (int c = 0; c < NCHUNK; ++c) {
            float kv = Krow[c * 32];
            float2 k2 = make_float2(kv, kv);
            ffma2(s01[c], q01, k2);
            ffma2(s23[c], q23, k2);
        }
    }

    // ---- scale + band mask ----
    #pragma unroll
    for (int c = 0; c < NCHUNK; ++c) {
        int kk = a + c * 32 + lane;
        int k  = k_lo + kk;
        bool inr = (kk <= b);
        bool v0 = inr && (k >= qg0     - (WIN-1)) && (k <= qg0     + (WIN-1));
        bool v1 = inr && (k >= qg0 + 1 - (WIN-1)) && (k <= qg0 + 1 + (WIN-1));
        bool v2 = inr && (k >= qg0 + 2 - (WIN-1)) && (k <= qg0 + 2 + (WIN-1));
        bool v3 = inr && (k >= qg0 + 3 - (WIN-1)) && (k <= qg0 + 3 + (WIN-1));
        s01[c].x = v0 ? s01[c].x * 0.125f : -INFINITY;
        s01[c].y = v1 ? s01[c].y * 0.125f : -INFINITY;
        s23[c].x = v2 ? s23[c].x * 0.125f : -INFINITY;
        s23[c].y = v3 ? s23[c].y * 0.125f : -INFINITY;
    }

    // ---- softmax (two query-pairs) ----
    {
        float2 mx = make_float2(-INFINITY, -INFINITY);
        #pragma unroll
        for (int c = 0; c < NCHUNK; ++c) {
            mx.x = fmaxf(mx.x, s01[c].x); mx.y = fmaxf(mx.y, s01[c].y);
        }
        #pragma unroll
        for (int off = 16; off > 0; off >>= 1) {
            mx.x = fmaxf(mx.x, __shfl_xor_sync(0xffffffffu, mx.x, off));
            mx.y = fmaxf(mx.y, __shfl_xor_sync(0xffffffffu, mx.y, off));
        }
        float2 sm = make_float2(0.f, 0.f);
        #pragma unroll
        for (int c = 0; c < NCHUNK; ++c) {
            s01[c].x = __expf(s01[c].x - mx.x); sm.x += s01[c].x;
            s01[c].y = __expf(s01[c].y - mx.y); sm.y += s01[c].y;
        }
        #pragma unroll
        for (int off = 16; off > 0; off >>= 1) {
            sm.x += __shfl_xor_sync(0xffffffffu, sm.x, off);
            sm.y += __shfl_xor_sync(0xffffffffu, sm.y, off);
        }
        float2 inv = make_float2(1.f / sm.x, 1.f / sm.y);
        #pragma unroll
        for (int c = 0; c < NCHUNK; ++c) { s01[c].x *= inv.x; s01[c].y *= inv.y; }
    }
    {
        float2 mx = make_float2(-INFINITY, -INFINITY);
        #pragma unroll
        for (int c = 0; c < NCHUNK; ++c) {
            mx.x = fmaxf(mx.x, s23[c].x); mx.y = fmaxf(mx.y, s23[c].y);
        }
        #pragma unroll
        for (int off = 16; off > 0; off >>= 1) {
            mx.x = fmaxf(mx.x, __shfl_xor_sync(0xffffffffu, mx.x, off));
            mx.y = fmaxf(mx.y, __shfl_xor_sync(0xffffffffu, mx.y, off));
        }
        float2 sm = make_float2(0.f, 0.f);
        #pragma unroll
        for (int c = 0; c < NCHUNK; ++c) {
            s23[c].x = __expf(s23[c].x - mx.x); sm.x += s23[c].x;
            s23[c].y = __expf(s23[c].y - mx.y); sm.y += s23[c].y;
        }
        #pragma unroll
        for (int off = 16; off > 0; off >>= 1) {
            sm.x += __shfl_xor_sync(0xffffffffu, sm.x, off);
            sm.y += __shfl_xor_sync(0xffffffffu, sm.y, off);
        }
        float2 inv = make_float2(1.f / sm.x, 1.f / sm.y);
        #pragma unroll
        for (int c = 0; c < NCHUNK; ++c) { s23[c].x *= inv.x; s23[c].y *= inv.y; }
    }

    // ---- write attn band values (coalesced across lanes) ----
    #pragma unroll
    for (int c = 0; c < NCHUNK; ++c) {
        int kk = a + c * 32 + lane;
        int k  = k_lo + kk;
        bool inr = (kk <= b);
        if (inr && k >= qg0     - (WIN-1) && k <= qg0     + (WIN-1))
            attn_base[(size_t)(qg0    ) * S_LEN + k] = s01[c].x;
        if (inr && k >= qg0 + 1 - (WIN-1) && k <= qg0 + 1 + (WIN-1))
            attn_base[(size_t)(qg0 + 1) * S_LEN + k] = s01[c].y;
        if (inr && k >= qg0 + 2 - (WIN-1) && k <= qg0 + 2 + (WIN-1))
            attn_base[(size_t)(qg0 + 2) * S_LEN + k] = s23[c].x;
        if (inr && k >= qg0 + 3 - (WIN-1) && k <= qg0 + 3 + (WIN-1))
            attn_base[(size_t)(qg0 + 3) * S_LEN + k] = s23[c].y;
    }

    // ---- context: packed f32x2, V via interleaved LDS.64 ----
    float2 cA01 = make_float2(0.f, 0.f), cA23 = make_float2(0.f, 0.f);
    float2 cB01 = make_float2(0.f, 0.f), cB23 = make_float2(0.f, 0.f);

    float* myPs = Ps + w * 128;
    #pragma unroll
    for (int c = 0; c < NCHUNK; ++c) {
        const int kkb = a + c * 32;
        const int nk  = min(32, b - kkb + 1);
        if (nk <= 0) continue;
        *(float4*)(myPs + lane * 4) = make_float4(s01[c].x, s01[c].y, s23[c].x, s23[c].y);
        __syncwarp();
        for (int j = 0; j < nk; ++j) {
            float4 p  = *(const float4*)(myPs + j * 4);
            float2 v2 = Vs2[(kkb + j) * 32 + lane];
            float2 p01 = make_float2(p.x, p.y);
            float2 p23 = make_float2(p.z, p.w);
            float2 vx = make_float2(v2.x, v2.x);
            float2 vy = make_float2(v2.y, v2.y);
            ffma2(cA01, p01, vx);
            ffma2(cA23, p23, vx);
            ffma2(cB01, p01, vy);
            ffma2(cB23, p23, vy);
        }
        __syncwarp();
    }

    float* ctx_base = ctx_out + ((size_t)bh * S_LEN + qg0) * DH;
    ctx_base[0 * DH + lane]      = cA01.x;
    ctx_base[0 * DH + lane + 32] = cB01.x;
    ctx_base[1 * DH + lane]      = cA01.y;
    ctx_base[1 * DH + lane + 32] = cB01.y;
    ctx_base[2 * DH + lane]      = cA23.x;
    ctx_base[2 * DH + lane + 32] = cB23.x;
    ctx_base[3 * DH + lane]      = cA23.y;
    ctx_base[3 * DH + lane + 32] = cB23.y;
}

extern "C" void kernel_launch(void* const* d_in, const int* in_sizes, int n_in,
                              void* d_out, int out_size)
{
    const float* Q = (const float*)d_in[0];
    const float* K = (const float*)d_in[1];
    const float* V = (const float*)d_in[2];

    float* out  = (float*)d_out;
    float* ctx  = out;                                 // [B,H,S,D] first
    float* attn = out + (size_t)NB * NH * S_LEN * DH;  // then [B,H,S,S]

    cudaFuncSetAttribute(band_attn_kernel,
                         cudaFuncAttributeMaxDynamicSharedMemorySize, SMEM_BYTES);

    dim3 grid(S_LEN / TQ, NH, NB);
    band_attn_kernel<<<grid, NTHREADS, SMEM_BYTES>>>(Q, K, V, ctx, attn);
}

// round 3
// speedup vs baseline: 1.4499x; 1.2327x over previous
#include <cuda_runtime.h>
#include <math.h>

#define S_LEN    2048
#define DH       64
#define NB       2
#define NH       8
#define WIN      128
#define TQ       128
#define NTHREADS 1024
#define NWARPS   32
#define NCHUNK   9

// Shared memory layout (floats)
#define KTS     383                  // K^T row stride (odd -> conflict-free d-writes)
#define KTROWS  382                  // max keys in a TQ=128 window
#define QTS     132                  // Q^T row stride (mult of 4, +4 pad)
#define SM_KT   (DH * KTS)           // 24512
#define SM_VS   (KTROWS * 32 * 2)    // 24448 floats (float2 interleaved)
#define SM_QT   (DH * QTS)           // 8448  (Ps overlaid here: 32*128=4096 <= 8448)
#define SM_FLOATS (SM_KT + SM_VS + SM_QT)
#define SMEM_BYTES (SM_FLOATS * 4)   // 229632 bytes

// packed f32x2 FMA: d = a*b + d  (sm_100+ FFMA2)
__device__ __forceinline__ void ffma2(float2& d, float2 a, float2 b) {
    asm("{\n\t"
        ".reg .b64 ra, rb, rd;\n\t"
        "mov.b64 ra, {%2, %3};\n\t"
        "mov.b64 rb, {%4, %5};\n\t"
        "mov.b64 rd, {%0, %1};\n\t"
        "fma.rn.f32x2 rd, ra, rb, rd;\n\t"
        "mov.b64 {%0, %1}, rd;\n\t"
        "}"
        : "+f"(d.x), "+f"(d.y)
        : "f"(a.x), "f"(a.y), "f"(b.x), "f"(b.y));
}

__global__ void __launch_bounds__(NTHREADS, 1)
band_attn_kernel(const float* __restrict__ Q,
                 const float* __restrict__ K,
                 const float* __restrict__ V,
                 float* __restrict__ ctx_out,
                 float* __restrict__ attn_out)
{
    extern __shared__ float smem[];
    float*  Kt  = smem;                       // [DH][KTS]
    float2* Vs2 = (float2*)(Kt + SM_KT);      // [KTROWS][32]: (v[d], v[d+32])
    float*  Qt  = (float*)(Vs2) + SM_VS;      // [DH][QTS]   (score phase only)
    float*  Ps  = Qt;                         // [32 warps][128]  (context phase only)

    const int tid  = threadIdx.x;
    const int w    = tid >> 5;
    const int lane = tid & 31;
    const int bh   = blockIdx.z * NH + blockIdx.y;
    const int q0   = blockIdx.x * TQ;

    const int k_lo = max(0, q0 - (WIN - 1));
    const int k_hi = min(S_LEN - 1, q0 + TQ - 1 + (WIN - 1));
    const int cnt  = k_hi - k_lo + 1;   // <= 382

    const float* Qg = Q + (size_t)bh * S_LEN * DH;
    const float* Kg = K + (size_t)bh * S_LEN * DH;
    const float* Vg = V + (size_t)bh * S_LEN * DH;

    // ---- load tiles into smem (issue global loads first) ----
    for (int idx = tid; idx < TQ * DH; idx += NTHREADS) {
        int q = idx >> 6, d = idx & 63;
        Qt[d * QTS + q] = Qg[(size_t)(q0 + q) * DH + d];
    }
    for (int idx = tid; idx < cnt * DH; idx += NTHREADS) {
        int kk = idx >> 6, d = idx & 63;
        Kt[d * KTS + kk] = Kg[(size_t)(k_lo + kk) * DH + d];
    }
    for (int idx = tid; idx < cnt * 32; idx += NTHREADS) {
        int kk = idx >> 5, l = idx & 31;
        Vs2[kk * 32 + l] = make_float2(Vg[(size_t)(k_lo + kk) * DH + l],
                                       Vg[(size_t)(k_lo + kk) * DH + l + 32]);
    }

    // ---- zero-fill attn rows outside band (fire-and-forget stores) ----
    float* attn_base = attn_out + (size_t)bh * S_LEN * S_LEN;
    {
        float* tile0 = attn_base + (size_t)q0 * S_LEN;
        const int m  = tid & 511;           // float4 chunk within a row
        const int rp = tid >> 9;            // row parity (2 rows per iter)
        const float4 z4 = make_float4(0.f, 0.f, 0.f, 0.f);
        #pragma unroll 4
        for (int r2 = 0; r2 < TQ / 2; ++r2) {
            int r  = r2 * 2 + rp;
            int qg = q0 + r;
            int lo = max(0, qg - (WIN - 1));
            int hi = min(S_LEN - 1, qg + (WIN - 1));
            if (4 * m + 3 < lo || 4 * m > hi)
                ((float4*)(tile0 + (size_t)r * S_LEN))[m] = z4;
        }
        if (tid < TQ) {
            int qg = q0 + tid;
            int lo = max(0, qg - (WIN - 1));
            int hi = min(S_LEN - 1, qg + (WIN - 1));
            float* row = tile0 + (size_t)tid * S_LEN;
            for (int c = lo & ~3; c < lo; ++c) row[c] = 0.f;
            int e = (hi + 4) & ~3;
            if (e > S_LEN) e = S_LEN;
            for (int c = hi + 1; c < e; ++c) row[c] = 0.f;
        }
    }
    __syncthreads();

    // ---- per-warp: 4 consecutive queries ----
    const int qbase = w * 4;
    const int qg0   = q0 + qbase;
    const int a = max(0, qg0 - (WIN - 1)) - k_lo;
    const int b = min(S_LEN - 1, qg0 + 3 + (WIN - 1)) - k_lo;

    // ---- scores (packed f32x2: two queries per FMA) ----
    float2 s01[NCHUNK], s23[NCHUNK];
    #pragma unroll
    for (int c = 0; c < NCHUNK; ++c) {
        s01[c] = make_float2(0.f, 0.f);
        s23[c] = make_float2(0.f, 0.f);
    }

    #pragma unroll 4
    for (int d = 0; d < DH; ++d) {
        const float4 qv = *(const float4*)(Qt + d * QTS + qbase);
        const float2 q01 = make_float2(qv.x, qv.y);
        const float2 q23 = make_float2(qv.z, qv.w);
        const float* Krow = Kt + d * KTS + a + lane;
        #pragma unroll
        for (int c = 0; c < NCHUNK; ++c) {
            float kv = Krow[c * 32];
            float2 k2 = make_float2(kv, kv);
            ffma2(s01[c], q01, k2);
            ffma2(s23[c], q23, k2);
        }
    }

    // ---- scale + band mask ----
    #pragma unroll
    for (int c = 0; c < NCHUNK; ++c) {
        int kk = a + c * 32 + lane;
        int k  = k_lo + kk;
        bool inr = (kk <= b);
        bool v0 = inr && (k >= qg0     - (WIN-1)) && (k <= qg0     + (WIN-1));
        bool v1 = inr && (k >= qg0 + 1 - (WIN-1)) && (k <= qg0 + 1 + (WIN-1));
        bool v2 = inr && (k >= qg0 + 2 - (WIN-1)) && (k <= qg0 + 2 + (WIN-1));
        bool v3 = inr && (k >= qg0 + 3 - (WIN-1)) && (k <= qg0 + 3 + (WIN-1));
        s01[c].x = v0 ? s01[c].x * 0.125f : -INFINITY;
        s01[c].y = v1 ? s01[c].y * 0.125f : -INFINITY;
        s23[c].x = v2 ? s23[c].x * 0.125f : -INFINITY;
        s23[c].y = v3 ? s23[c].y * 0.125f : -INFINITY;
    }

    // ---- softmax (two query-pairs) ----
    {
        float2 mx = make_float2(-INFINITY, -INFINITY);
        #pragma unroll
        for (int c = 0; c < NCHUNK; ++c) {
            mx.x = fmaxf(mx.x, s01[c].x); mx.y = fmaxf(mx.y, s01[c].y);
        }
        #pragma unroll
        for (int off = 16; off > 0; off >>= 1) {
            mx.x = fmaxf(mx.x, __shfl_xor_sync(0xffffffffu, mx.x, off));
            mx.y = fmaxf(mx.y, __shfl_xor_sync(0xffffffffu, mx.y, off));
        }
        float2 sm = make_float2(0.f, 0.f);
        #pragma unroll
        for (int c = 0; c < NCHUNK; ++c) {
            s01[c].x = __expf(s01[c].x - mx.x); sm.x += s01[c].x;
            s01[c].y = __expf(s01[c].y - mx.y); sm.y += s01[c].y;
        }
        #pragma unroll
        for (int off = 16; off > 0; off >>= 1) {
            sm.x += __shfl_xor_sync(0xffffffffu, sm.x, off);
            sm.y += __shfl_xor_sync(0xffffffffu, sm.y, off);
        }
        float2 inv = make_float2(1.f / sm.x, 1.f / sm.y);
        #pragma unroll
        for (int c = 0; c < NCHUNK; ++c) { s01[c].x *= inv.x; s01[c].y *= inv.y; }
    }
    {
        float2 mx = make_float2(-INFINITY, -INFINITY);
        #pragma unroll
        for (int c = 0; c < NCHUNK; ++c) {
            mx.x = fmaxf(mx.x, s23[c].x); mx.y = fmaxf(mx.y, s23[c].y);
        }
        #pragma unroll
        for (int off = 16; off > 0; off >>= 1) {
            mx.x = fmaxf(mx.x, __shfl_xor_sync(0xffffffffu, mx.x, off));
            mx.y = fmaxf(mx.y, __shfl_xor_sync(0xffffffffu, mx.y, off));
        }
        float2 sm = make_float2(0.f, 0.f);
        #pragma unroll
        for (int c = 0; c < NCHUNK; ++c) {
            s23[c].x = __expf(s23[c].x - mx.x); sm.x += s23[c].x;
            s23[c].y = __expf(s23[c].y - mx.y); sm.y += s23[c].y;
        }
        #pragma unroll
        for (int off = 16; off > 0; off >>= 1) {
            sm.x += __shfl_xor_sync(0xffffffffu, sm.x, off);
            sm.y += __shfl_xor_sync(0xffffffffu, sm.y, off);
        }
        float2 inv = make_float2(1.f / sm.x, 1.f / sm.y);
        #pragma unroll
        for (int c = 0; c < NCHUNK; ++c) { s23[c].x *= inv.x; s23[c].y *= inv.y; }
    }

    // ---- write attn band values (coalesced across lanes) ----
    #pragma unroll
    for (int c = 0; c < NCHUNK; ++c) {
        int kk = a + c * 32 + lane;
        int k  = k_lo + kk;
        bool inr = (kk <= b);
        if (inr && k >= qg0     - (WIN-1) && k <= qg0     + (WIN-1))
            attn_base[(size_t)(qg0    ) * S_LEN + k] = s01[c].x;
        if (inr && k >= qg0 + 1 - (WIN-1) && k <= qg0 + 1 + (WIN-1))
            attn_base[(size_t)(qg0 + 1) * S_LEN + k] = s01[c].y;
        if (inr && k >= qg0 + 2 - (WIN-1) && k <= qg0 + 2 + (WIN-1))
            attn_base[(size_t)(qg0 + 2) * S_LEN + k] = s23[c].x;
        if (inr && k >= qg0 + 3 - (WIN-1) && k <= qg0 + 3 + (WIN-1))
            attn_base[(size_t)(qg0 + 3) * S_LEN + k] = s23[c].y;
    }

    // Qt is dead from here; Ps overlays it. Make sure every warp finished
    // reading Qt before any warp writes Ps.
    __syncthreads();

    // ---- context: packed f32x2, V via interleaved LDS.64 ----
    float2 cA01 = make_float2(0.f, 0.f), cA23 = make_float2(0.f, 0.f);
    float2 cB01 = make_float2(0.f, 0.f), cB23 = make_float2(0.f, 0.f);

    float* myPs = Ps + w * 128;
    #pragma unroll
    for (int c = 0; c < NCHUNK; ++c) {
        const int kkb = a + c * 32;
        const int nk  = min(32, b - kkb + 1);
        if (nk <= 0) continue;
        *(float4*)(myPs + lane * 4) = make_float4(s01[c].x, s01[c].y, s23[c].x, s23[c].y);
        __syncwarp();
        for (int j = 0; j < nk; ++j) {
            float4 p  = *(const float4*)(myPs + j * 4);
            float2 v2 = Vs2[(kkb + j) * 32 + lane];
            float2 p01 = make_float2(p.x, p.y);
            float2 p23 = make_float2(p.z, p.w);
            float2 vx = make_float2(v2.x, v2.x);
            float2 vy = make_float2(v2.y, v2.y);
            ffma2(cA01, p01, vx);
            ffma2(cA23, p23, vx);
            ffma2(cB01, p01, vy);
            ffma2(cB23, p23, vy);
        }
        __syncwarp();
    }

    float* ctx_base = ctx_out + ((size_t)bh * S_LEN + qg0) * DH;
    ctx_base[0 * DH + lane]      = cA01.x;
    ctx_base[0 * DH + lane + 32] = cB01.x;
    ctx_base[1 * DH + lane]      = cA01.y;
    ctx_base[1 * DH + lane + 32] = cB01.y;
    ctx_base[2 * DH + lane]      = cA23.x;
    ctx_base[2 * DH + lane + 32] = cB23.x;
    ctx_base[3 * DH + lane]      = cA23.y;
    ctx_base[3 * DH + lane + 32] = cB23.y;
}

extern "C" void kernel_launch(void* const* d_in, const int* in_sizes, int n_in,
                              void* d_out, int out_size)
{
    const float* Q = (const float*)d_in[0];
    const float* K = (const float*)d_in[1];
    const float* V = (const float*)d_in[2];

    float* out  = (float*)d_out;
    float* ctx  = out;                                 // [B,H,S,D] first
    float* attn = out + (size_t)NB * NH * S_LEN * DH;  // then [B,H,S,S]

    cudaFuncSetAttribute(band_attn_kernel,
                         cudaFuncAttributeMaxDynamicSharedMemorySize, SMEM_BYTES);

    dim3 grid(S_LEN / TQ, NH, NB);
    band_attn_kernel<<<grid, NTHREADS, SMEM_BYTES>>>(Q, K, V, ctx, attn);
}

// round 4
// speedup vs baseline: 1.4524x; 1.0017x over previous
#include <cuda_runtime.h>
#include <math.h>

#define S_LEN    2048
#define DH       64
#define NB       2
#define NH       8
#define WIN      128
#define TQ       128
#define NTHREADS 1024
#define NWARPS   32
#define NCHUNK   9

// Shared memory layout (floats)
#define KTS     383                  // K^T row stride (odd -> conflict-free d-writes)
#define KTROWS  382                  // max keys in a TQ=128 window
#define QTS     132                  // Q^T row stride (mult of 4, +4 pad)
#define SM_KT   (DH * KTS)           // 24512
#define SM_VS   (KTROWS * 32 * 2)    // 24448 floats (float2 interleaved)
#define SM_QT   (DH * QTS)           // 8448  (Ps overlaid here: 32*128=4096 <= 8448)
#define SM_FLOATS (SM_KT + SM_VS + SM_QT)
#define SMEM_BYTES (SM_FLOATS * 4)   // 229632 bytes

// packed f32x2 FMA: d = a*b + d  (sm_100+ FFMA2)
__device__ __forceinline__ void ffma2(float2& d, float2 a, float2 b) {
    asm("{\n\t"
        ".reg .b64 ra, rb, rd;\n\t"
        "mov.b64 ra, {%2, %3};\n\t"
        "mov.b64 rb, {%4, %5};\n\t"
        "mov.b64 rd, {%0, %1};\n\t"
        "fma.rn.f32x2 rd, ra, rb, rd;\n\t"
        "mov.b64 {%0, %1}, rd;\n\t"
        "}"
        : "+f"(d.x), "+f"(d.y)
        : "f"(a.x), "f"(a.y), "f"(b.x), "f"(b.y));
}

__global__ void __launch_bounds__(NTHREADS, 1)
band_attn_kernel(const float* __restrict__ Q,
                 const float* __restrict__ K,
                 const float* __restrict__ V,
                 float* __restrict__ ctx_out,
                 float* __restrict__ attn_out)
{
    extern __shared__ float smem[];
    float*  Kt  = smem;                       // [DH][KTS]
    float2* Vs2 = (float2*)(Kt + SM_KT);      // [KTROWS][32]: (v[d], v[d+32])
    float*  Qt  = (float*)(Vs2) + SM_VS;      // [DH][QTS]   (score phase only)
    float*  Ps  = Qt;                         // [32 warps][128]  (context phase only)

    const int tid  = threadIdx.x;
    const int w    = tid >> 5;
    const int lane = tid & 31;
    const int bh   = blockIdx.z * NH + blockIdx.y;
    const int q0   = blockIdx.x * TQ;

    const int k_lo = max(0, q0 - (WIN - 1));
    const int k_hi = min(S_LEN - 1, q0 + TQ - 1 + (WIN - 1));
    const int cnt  = k_hi - k_lo + 1;   // <= 382

    const float* Qg = Q + (size_t)bh * S_LEN * DH;
    const float* Kg = K + (size_t)bh * S_LEN * DH;
    const float* Vg = V + (size_t)bh * S_LEN * DH;

    // ---- load tiles into smem (issue global loads first) ----
    for (int idx = tid; idx < TQ * DH; idx += NTHREADS) {
        int q = idx >> 6, d = idx & 63;
        Qt[d * QTS + q] = Qg[(size_t)(q0 + q) * DH + d];
    }
    for (int idx = tid; idx < cnt * DH; idx += NTHREADS) {
        int kk = idx >> 6, d = idx & 63;
        Kt[d * KTS + kk] = Kg[(size_t)(k_lo + kk) * DH + d];
    }
    for (int idx = tid; idx < cnt * 32; idx += NTHREADS) {
        int kk = idx >> 5, l = idx & 31;
        Vs2[kk * 32 + l] = make_float2(Vg[(size_t)(k_lo + kk) * DH + l],
                                       Vg[(size_t)(k_lo + kk) * DH + l + 32]);
    }

    // ---- zero-fill attn rows outside band (fire-and-forget stores) ----
    float* attn_base = attn_out + (size_t)bh * S_LEN * S_LEN;
    {
        float* tile0 = attn_base + (size_t)q0 * S_LEN;
        const int m  = tid & 511;           // float4 chunk within a row
        const int rp = tid >> 9;            // row parity (2 rows per iter)
        const float4 z4 = make_float4(0.f, 0.f, 0.f, 0.f);
        #pragma unroll 4
        for (int r2 = 0; r2 < TQ / 2; ++r2) {
            int r  = r2 * 2 + rp;
            int qg = q0 + r;
            int lo = max(0, qg - (WIN - 1));
            int hi = min(S_LEN - 1, qg + (WIN - 1));
            if (4 * m + 3 < lo || 4 * m > hi)
                ((float4*)(tile0 + (size_t)r * S_LEN))[m] = z4;
        }
        if (tid < TQ) {
            int qg = q0 + tid;
            int lo = max(0, qg - (WIN - 1));
            int hi = min(S_LEN - 1, qg + (WIN - 1));
            float* row = tile0 + (size_t)tid * S_LEN;
            for (int c = lo & ~3; c < lo; ++c) row[c] = 0.f;
            int e = (hi + 4) & ~3;
            if (e > S_LEN) e = S_LEN;
            for (int c = hi + 1; c < e; ++c) row[c] = 0.f;
        }
    }
    __syncthreads();

    // ---- per-warp: 4 consecutive queries ----
    const int qbase = w * 4;
    const int qg0   = q0 + qbase;
    const int a = max(0, qg0 - (WIN - 1)) - k_lo;
    const int b = min(S_LEN - 1, qg0 + 3 + (WIN - 1)) - k_lo;

    // ---- scores (packed f32x2: two queries per FMA) ----
    float2 s01[NCHUNK], s23[NCHUNK];
    #pragma unroll
    for (int c = 0; c < NCHUNK; ++c) {
        s01[c] = make_float2(0.f, 0.f);
        s23[c] = make_float2(0.f, 0.f);
    }

    #pragma unroll 4
    for (int d = 0; d < DH; ++d) {
        const float4 qv = *(const float4*)(Qt + d * QTS + qbase);
        const float2 q01 = make_float2(qv.x, qv.y);
        const float2 q23 = make_float2(qv.z, qv.w);
        const float* Krow = Kt + d * KTS + a + lane;
        #pragma unroll
        for (int c = 0; c < NCHUNK; ++c) {
            float kv = Krow[c * 32];
            float2 k2 = make_float2(kv, kv);
            ffma2(s01[c], q01, k2);
            ffma2(s23[c], q23, k2);
        }
    }

    // ---- scale + band mask ----
    #pragma unroll
    for (int c = 0; c < NCHUNK; ++c) {
        int kk = a + c * 32 + lane;
        int k  = k_lo + kk;
        bool inr = (kk <= b);
        bool v0 = inr && (k >= qg0     - (WIN-1)) && (k <= qg0     + (WIN-1));
        bool v1 = inr && (k >= qg0 + 1 - (WIN-1)) && (k <= qg0 + 1 + (WIN-1));
        bool v2 = inr && (k >= qg0 + 2 - (WIN-1)) && (k <= qg0 + 2 + (WIN-1));
        bool v3 = inr && (k >= qg0 + 3 - (WIN-1)) && (k <= qg0 + 3 + (WIN-1));
        s01[c].x = v0 ? s01[c].x * 0.125f : -INFINITY;
        s01[c].y = v1 ? s01[c].y * 0.125f : -INFINITY;
        s23[c].x = v2 ? s23[c].x * 0.125f : -INFINITY;
        s23[c].y = v3 ? s23[c].y * 0.125f : -INFINITY;
    }

    // ---- softmax (two query-pairs) ----
    {
        float2 mx = make_float2(-INFINITY, -INFINITY);
        #pragma unroll
        for (int c = 0; c < NCHUNK; ++c) {
            mx.x = fmaxf(mx.x, s01[c].x); mx.y = fmaxf(mx.y, s01[c].y);
        }
        #pragma unroll
        for (int off = 16; off > 0; off >>= 1) {
            mx.x = fmaxf(mx.x, __shfl_xor_sync(0xffffffffu, mx.x, off));
            mx.y = fmaxf(mx.y, __shfl_xor_sync(0xffffffffu, mx.y, off));
        }
        float2 sm = make_float2(0.f, 0.f);
        #pragma unroll
        for (int c = 0; c < NCHUNK; ++c) {
            s01[c].x = __expf(s01[c].x - mx.x); sm.x += s01[c].x;
            s01[c].y = __expf(s01[c].y - mx.y); sm.y += s01[c].y;
        }
        #pragma unroll
        for (int off = 16; off > 0; off >>= 1) {
            sm.x += __shfl_xor_sync(0xffffffffu, sm.x, off);
            sm.y += __shfl_xor_sync(0xffffffffu, sm.y, off);
        }
        float2 inv = make_float2(1.f / sm.x, 1.f / sm.y);
        #pragma unroll
        for (int c = 0; c < NCHUNK; ++c) { s01[c].x *= inv.x; s01[c].y *= inv.y; }
    }
    {
        float2 mx = make_float2(-INFINITY, -INFINITY);
        #pragma unroll
        for (int c = 0; c < NCHUNK; ++c) {
            mx.x = fmaxf(mx.x, s23[c].x); mx.y = fmaxf(mx.y, s23[c].y);
        }
        #pragma unroll
        for (int off = 16; off > 0; off >>= 1) {
            mx.x = fmaxf(mx.x, __shfl_xor_sync(0xffffffffu, mx.x, off));
            mx.y = fmaxf(mx.y, __shfl_xor_sync(0xffffffffu, mx.y, off));
        }
        float2 sm = make_float2(0.f, 0.f);
        #pragma unroll
        for (int c = 0; c < NCHUNK; ++c) {
            s23[c].x = __expf(s23[c].x - mx.x); sm.x += s23[c].x;
            s23[c].y = __expf(s23[c].y - mx.y); sm.y += s23[c].y;
        }
        #pragma unroll
        for (int off = 16; off > 0; off >>= 1) {
            sm.x += __shfl_xor_sync(0xffffffffu, sm.x, off);
            sm.y += __shfl_xor_sync(0xffffffffu, sm.y, off);
        }
        float2 inv = make_float2(1.f / sm.x, 1.f / sm.y);
        #pragma unroll
        for (int c = 0; c < NCHUNK; ++c) { s23[c].x *= inv.x; s23[c].y *= inv.y; }
    }

    // ---- write attn band values (coalesced across lanes) ----
    #pragma unroll
    for (int c = 0; c < NCHUNK; ++c) {
        int kk = a + c * 32 + lane;
        int k  = k_lo + kk;
        bool inr = (kk <= b);
        if (inr && k >= qg0     - (WIN-1) && k <= qg0     + (WIN-1))
            attn_base[(size_t)(qg0    ) * S_LEN + k] = s01[c].x;
        if (inr && k >= qg0 + 1 - (WIN-1) && k <= qg0 + 1 + (WIN-1))
            attn_base[(size_t)(qg0 + 1) * S_LEN + k] = s01[c].y;
        if (inr && k >= qg0 + 2 - (WIN-1) && k <= qg0 + 2 + (WIN-1))
            attn_base[(size_t)(qg0 + 2) * S_LEN + k] = s23[c].x;
        if (inr && k >= qg0 + 3 - (WIN-1) && k <= qg0 + 3 + (WIN-1))
            attn_base[(size_t)(qg0 + 3) * S_LEN + k] = s23[c].y;
    }

    // Qt is dead from here; Ps overlays it. Make sure every warp finished
    // reading Qt before any warp writes Ps.
    __syncthreads();

    // ---- context: packed f32x2, V via interleaved LDS.64 ----
    float2 cA01 = make_float2(0.f, 0.f), cA23 = make_float2(0.f, 0.f);
    float2 cB01 = make_float2(0.f, 0.f), cB23 = make_float2(0.f, 0.f);

    float* myPs = Ps + w * 128;
    #pragma unroll
    for (int c = 0; c < NCHUNK; ++c) {
        const int kkb = a + c * 32;
        const int nk  = min(32, b - kkb + 1);
        if (nk <= 0) continue;
        *(float4*)(myPs + lane * 4) = make_float4(s01[c].x, s01[c].y, s23[c].x, s23[c].y);
        __syncwarp();
        for (int j = 0; j < nk; ++j) {
            float4 p  = *(const float4*)(myPs + j * 4);
            float2 v2 = Vs2[(kkb + j) * 32 + lane];
            float2 p01 = make_float2(p.x, p.y);
            float2 p23 = make_float2(p.z, p.w);
            float2 vx = make_float2(v2.x, v2.x);
            float2 vy = make_float2(v2.y, v2.y);
            ffma2(cA01, p01, vx);
            ffma2(cA23, p23, vx);
            ffma2(cB01, p01, vy);
            ffma2(cB23, p23, vy);
        }
        __syncwarp();
    }

    float* ctx_base = ctx_out + ((size_t)bh * S_LEN + qg0) * DH;
    ctx_base[0 * DH + lane]      = cA01.x;
    ctx_base[0 * DH + lane + 32] = cB01.x;
    ctx_base[1 * DH + lane]      = cA01.y;
    ctx_base[1 * DH + lane + 32] = cB01.y;
    ctx_base[2 * DH + lane]      = cA23.x;
    ctx_base[2 * DH + lane + 32] = cB23.x;
    ctx_base[3 * DH + lane]      = cA23.y;
    ctx_base[3 * DH + lane + 32] = cB23.y;
}

extern "C" void kernel_launch(void* const* d_in, const int* in_sizes, int n_in,
                              void* d_out, int out_size)
{
    const float* Q = (const float*)d_in[0];
    const float* K = (const float*)d_in[1];
    const float* V = (const float*)d_in[2];

    float* out  = (float*)d_out;
    float* ctx  = out;                                 // [B,H,S,D] first
    float* attn = out + (size_t)NB * NH * S_LEN * DH;  // then [B,H,S,S]

    cudaFuncSetAttribute(band_attn_kernel,
                         cudaFuncAttributeMaxDynamicSharedMemorySize, SMEM_BYTES);

    dim3 grid(S_LEN / TQ, NH, NB);
    band_attn_kernel<<<grid, NTHREADS, SMEM_BYTES>>>(Q, K, V, ctx, attn);
}